// round 2
// baseline (speedup 1.0000x reference)
#include <cuda_runtime.h>
#include <math.h>

#define N_NODES 50000
#define EMB 35
#define DEG 32

// Scratch (static __device__ — no allocation allowed).
// Embedding / message rows padded to 36 floats for 16B alignment (float4 paths).
__device__ float g_emb[4][N_NODES * 36];   // transformed neighbor tables, [35]=0 pad
__device__ float g_sdst[4][N_NODES];       // new_emb @ att[EMB:]
__device__ float g_ssrc[4][N_NODES];       // features @ att[:EMB]
__device__ float g_m[4][N_NODES * 36];     // aggregated messages, [35]=junk(0)

struct Params {
    const float* fa; const float* fb;
    const int*   dst[4];
    const float* W[4]; const float* bv[4]; const float* att[4];
    const float* W1; const float* b1; const float* alpha; const float* W2; const float* b2;
    float* out;
};

// ---------------------------------------------------------------------------
// Kernel 1: per-agg linear transform + attention scores.
// agg 0/1 (ab pos/neg): table = feature_b @ W + b, score-src = feature_a
// agg 2/3 (ba pos/neg): table = feature_a @ W + b, score-src = feature_b
// One thread per row. W staged in shared, padded to 36 cols for float4 LDS.
// ---------------------------------------------------------------------------
__global__ void transform_kernel(Params p) {
    const int agg = blockIdx.y;
    __shared__ float Ws[35 * 36];
    __shared__ float bs[36];
    __shared__ float a1s[35];
    __shared__ float a2s[35];
    {
        const float* W = p.W[agg];
        for (int t = threadIdx.x; t < 35 * 36; t += blockDim.x) {
            int i = t / 36, c = t % 36;
            Ws[t] = (c < 35) ? W[i * 35 + c] : 0.0f;
        }
        const float* bb = p.bv[agg];
        for (int t = threadIdx.x; t < 36; t += blockDim.x) bs[t] = (t < 35) ? bb[t] : 0.0f;
        const float* at = p.att[agg];
        for (int t = threadIdx.x; t < 35; t += blockDim.x) { a1s[t] = at[t]; a2s[t] = at[35 + t]; }
    }
    __syncthreads();

    int r = blockIdx.x * blockDim.x + threadIdx.x;
    if (r >= N_NODES) return;

    const float* ftab = (agg < 2) ? p.fb : p.fa;   // rows being transformed
    const float* fsc  = (agg < 2) ? p.fa : p.fb;   // rows producing s_src

    float o[36];
#pragma unroll
    for (int c = 0; c < 36; c++) o[c] = bs[c];

    const float* fr = ftab + r * 35;
#pragma unroll 5
    for (int i = 0; i < 35; i++) {
        float fi = fr[i];
        const float4* wr = (const float4*)(Ws + i * 36);
#pragma unroll
        for (int q = 0; q < 9; q++) {
            float4 w = wr[q];
            o[4 * q + 0] += fi * w.x; o[4 * q + 1] += fi * w.y;
            o[4 * q + 2] += fi * w.z; o[4 * q + 3] += fi * w.w;
        }
    }

    float* om = g_emb[agg] + r * 36;
    float sd = 0.0f;
#pragma unroll
    for (int c = 0; c < 35; c++) { om[c] = o[c]; sd += o[c] * a2s[c]; }
    om[35] = 0.0f;                 // pad slot must be 0 (float4 gather tail)
    g_sdst[agg][r] = sd;

    const float* fr2 = fsc + r * 35;
    float s1 = 0.0f;
#pragma unroll
    for (int i = 0; i < 35; i++) s1 += fr2[i] * a1s[i];
    g_ssrc[agg][r] = s1;
}

// ---------------------------------------------------------------------------
// Kernel 2: attention aggregation. One warp per (agg, node).
// lane e owns edge e: d = dst[node*32+e], w = exp(elu01(s_src + s_dst[d])).
// Then 32 broadcast steps; lanes 0..8 gather the 36-float row as float4.
// ---------------------------------------------------------------------------
__global__ void aggregate_kernel(Params p) {
    int gw   = (blockIdx.x * blockDim.x + threadIdx.x) >> 5;
    int lane = threadIdx.x & 31;
    if (gw >= 4 * N_NODES) return;
    int agg  = gw / N_NODES;
    int node = gw - agg * N_NODES;

    int d = p.dst[agg][node * DEG + lane];
    float z  = g_ssrc[agg][node] + g_sdst[agg][d];
    float el = (z > 0.0f) ? z : 0.1f * expm1f(z);
    float w  = expf(el);

    // denominator: warp sum of w (always > 0)
    float den = w;
#pragma unroll
    for (int off = 16; off; off >>= 1) den += __shfl_xor_sync(0xffffffffu, den, off);

    const float* tab = g_emb[agg];
    float4 acc = make_float4(0.f, 0.f, 0.f, 0.f);
#pragma unroll
    for (int e = 0; e < 32; e++) {
        int   de = __shfl_sync(0xffffffffu, d, e);
        float we = __shfl_sync(0xffffffffu, w, e);
        if (lane < 9) {
            float4 v = *(const float4*)(tab + de * 36 + lane * 4);
            acc.x += we * v.x; acc.y += we * v.y;
            acc.z += we * v.z; acc.w += we * v.w;
        }
    }
    if (lane < 9) {
        float inv = 1.0f / den;
        float4 res = make_float4(acc.x * inv, acc.y * inv, acc.z * inv, acc.w * inv);
        *(float4*)(g_m[agg] + node * 36 + lane * 4) = res;
    }
}

// ---------------------------------------------------------------------------
// Kernel 3: shared update MLP: concat(f, m_pos, m_neg)[105] -> 70 (PReLU) -> 35.
// One thread per node. W1 stored TRANSPOSED + padded (70 x 108) in shared so
// the j-loop streams contiguous float4 against a constant-indexed x[108] in
// registers; o[36] accumulated directly (no h array, no local memory).
// ---------------------------------------------------------------------------
__global__ void __launch_bounds__(128) update_kernel(Params p) {
    __shared__ float W1Ts[70 * 108];
    __shared__ float W2s[70 * 36];
    __shared__ float b1s[70];
    __shared__ float b2s[36];
    __shared__ float als;

    for (int t = threadIdx.x; t < 70 * 108; t += blockDim.x) W1Ts[t] = 0.0f;
    for (int t = threadIdx.x; t < 70 * 36;  t += blockDim.x) W2s[t]  = 0.0f;
    __syncthreads();
    for (int t = threadIdx.x; t < 105 * 70; t += blockDim.x) {
        int i = t / 70, j = t % 70;
        W1Ts[j * 108 + i] = p.W1[t];
    }
    for (int t = threadIdx.x; t < 70 * 35; t += blockDim.x) {
        int j = t / 35, c = t % 35;
        W2s[j * 36 + c] = p.W2[t];
    }
    for (int t = threadIdx.x; t < 70; t += blockDim.x) b1s[t] = p.b1[t];
    for (int t = threadIdx.x; t < 36; t += blockDim.x) b2s[t] = (t < 35) ? p.b2[t] : 0.0f;
    if (threadIdx.x == 0) als = p.alpha[0];
    __syncthreads();

    int n = blockIdx.x * blockDim.x + threadIdx.x;
    if (n >= 2 * N_NODES) return;
    bool sideA = (n < N_NODES);
    int r = sideA ? n : n - N_NODES;
    const float* f  = (sideA ? p.fa : p.fb) + r * 35;
    const float* mp = (sideA ? g_m[0] : g_m[2]) + r * 36;
    const float* mn = (sideA ? g_m[1] : g_m[3]) + r * 36;

    float x[108];
#pragma unroll
    for (int i = 0; i < 35; i++) x[i]      = f[i];
#pragma unroll
    for (int i = 0; i < 35; i++) x[35 + i] = mp[i];
#pragma unroll
    for (int i = 0; i < 35; i++) x[70 + i] = mn[i];
    x[105] = x[106] = x[107] = 0.0f;

    float o[36];
#pragma unroll
    for (int c = 0; c < 36; c++) o[c] = b2s[c];
    float a = als;

#pragma unroll 2
    for (int j = 0; j < 70; j++) {
        float hj = b1s[j];
        const float4* wr = (const float4*)(W1Ts + j * 108);
#pragma unroll
        for (int q = 0; q < 27; q++) {
            float4 w = wr[q];
            hj += x[4 * q + 0] * w.x + x[4 * q + 1] * w.y
                + x[4 * q + 2] * w.z + x[4 * q + 3] * w.w;
        }
        hj = (hj > 0.0f) ? hj : a * hj;          // PReLU (single shared alpha)
        const float4* w2 = (const float4*)(W2s + j * 36);
#pragma unroll
        for (int q = 0; q < 9; q++) {
            float4 w = w2[q];
            o[4 * q + 0] += hj * w.x; o[4 * q + 1] += hj * w.y;
            o[4 * q + 2] += hj * w.z; o[4 * q + 3] += hj * w.w;
        }
    }

    float* op = p.out + n * 35;
#pragma unroll
    for (int c = 0; c < 35; c++) op[c] = o[c];
}

// ---------------------------------------------------------------------------
extern "C" void kernel_launch(void* const* d_in, const int* in_sizes, int n_in,
                              void* d_out, int out_size) {
    Params p;
    p.fa = (const float*)d_in[0];
    p.fb = (const float*)d_in[1];
    p.dst[0] = (const int*)d_in[2];   // dst_ab_pos
    p.dst[1] = (const int*)d_in[3];   // dst_ab_neg
    p.dst[2] = (const int*)d_in[4];   // dst_ba_pos
    p.dst[3] = (const int*)d_in[5];   // dst_ba_neg
    for (int k = 0; k < 4; k++) {
        p.W[k]   = (const float*)d_in[6 + 3 * k];
        p.bv[k]  = (const float*)d_in[7 + 3 * k];
        p.att[k] = (const float*)d_in[8 + 3 * k];
    }
    p.W1    = (const float*)d_in[18];
    p.b1    = (const float*)d_in[19];
    p.alpha = (const float*)d_in[20];
    p.W2    = (const float*)d_in[21];
    p.b2    = (const float*)d_in[22];
    p.out   = (float*)d_out;

    dim3 g1((N_NODES + 127) / 128, 4);
    transform_kernel<<<g1, 128>>>(p);

    long long total_threads = (long long)4 * N_NODES * 32;
    int blocks2 = (int)((total_threads + 255) / 256);
    aggregate_kernel<<<blocks2, 256>>>(p);

    update_kernel<<<(2 * N_NODES + 127) / 128, 128>>>(p);
}

// round 4
// speedup vs baseline: 1.0323x; 1.0323x over previous
#include <cuda_runtime.h>
#include <math.h>

#define N_NODES 50000
#define EMB 35
#define DEG 32

// Scratch (static __device__ — no allocation allowed).
__device__ float g_emb[4][N_NODES * 36];   // transformed tables, col35 = 0 pad
__device__ float g_sdst[4][N_NODES];
__device__ float g_ssrc[4][N_NODES];
__device__ float g_m[4][N_NODES * 36];     // aggregated messages

struct Params {
    const float* fa; const float* fb;
    const int*   dst[4];
    const float* W[4]; const float* bv[4]; const float* att[4];
    const float* W1; const float* b1; const float* alpha; const float* W2; const float* b2;
    float* out;
};

// ---- packed f32x2 helpers (sm_103a FFMA2 path) ------------------------------
__device__ __forceinline__ unsigned long long pack2(float lo, float hi) {
    unsigned long long r;
    asm("mov.b64 %0, {%1,%2};" : "=l"(r) : "f"(lo), "f"(hi));
    return r;
}
__device__ __forceinline__ void unpack2(unsigned long long v, float& lo, float& hi) {
    asm("mov.b64 {%0,%1}, %2;" : "=f"(lo), "=f"(hi) : "l"(v));
}
__device__ __forceinline__ void fma2(unsigned long long& d, unsigned long long a, unsigned long long b) {
    asm("fma.rn.f32x2 %0, %1, %2, %0;" : "+l"(d) : "l"(a), "l"(b));
}
// LDS.128 delivering two packed f32x2 operands (16B-aligned shared address).
__device__ __forceinline__ void lds_v2u64(const float* sp, unsigned long long& a, unsigned long long& b) {
    unsigned int addr = (unsigned int)__cvta_generic_to_shared(sp);
    asm("ld.shared.v2.u64 {%0,%1}, [%2];" : "=l"(a), "=l"(b) : "r"(addr));
}

// ---------------------------------------------------------------------------
// Kernel 1: per-agg transform + attention scores. Block = 128 rows.
// All global I/O goes through a stride-37 shared tile (coalesced GMEM,
// conflict-free LDS). MACs use FFMA2.
// ---------------------------------------------------------------------------
__global__ void __launch_bounds__(128) transform_kernel(Params p) {
    const int agg = blockIdx.y;
    __shared__ __align__(16) float Ws[35 * 36];   // padded cols, col35 = 0
    __shared__ __align__(16) float tile[128 * 37];
    __shared__ float bs[36], a1s[35], a2s[35];

    {
        const float* W = p.W[agg];
        for (int t = threadIdx.x; t < 35 * 36; t += 128) {
            int i = t / 36, c = t - 36 * i;
            Ws[t] = (c < 35) ? W[i * 35 + c] : 0.0f;
        }
        const float* bb = p.bv[agg];
        for (int t = threadIdx.x; t < 36; t += 128) bs[t] = (t < 35) ? bb[t] : 0.0f;
        const float* at = p.att[agg];
        for (int t = threadIdx.x; t < 35; t += 128) { a1s[t] = at[t]; a2s[t] = at[35 + t]; }
    }

    const int base = blockIdx.x * 128;
    const int cnt  = min(128, N_NODES - base);
    const int tid  = threadIdx.x;
    const float* ftab = (agg < 2) ? p.fb : p.fa;
    const float* fsc  = (agg < 2) ? p.fa : p.fb;

    // ---- phase A: s_src (coalesced stage, per-row dot) ----
    __syncthreads();
    for (int idx = tid; idx < cnt * 35; idx += 128) {
        int r = idx / 35, c = idx - 35 * r;
        tile[r * 37 + c] = fsc[base * 35 + idx];
    }
    __syncthreads();
    if (tid < cnt) {
        float s1 = 0.0f;
        const float* xr = tile + tid * 37;
#pragma unroll
        for (int i = 0; i < 35; i++) s1 += xr[i] * a1s[i];
        g_ssrc[agg][base + tid] = s1;
    }
    __syncthreads();

    // ---- phase B: new_emb = ftab @ W + b, s_dst ----
    for (int idx = tid; idx < cnt * 35; idx += 128) {
        int r = idx / 35, c = idx - 35 * r;
        tile[r * 37 + c] = ftab[base * 35 + idx];
    }
    __syncthreads();
    if (tid < cnt) {
        unsigned long long o2[18];
#pragma unroll
        for (int k = 0; k < 18; k++) o2[k] = pack2(bs[2 * k], bs[2 * k + 1]);
        const float* xr = tile + tid * 37;
#pragma unroll
        for (int i = 0; i < 35; i++) {
            float fi = xr[i];
            unsigned long long ff = pack2(fi, fi);
            const float* wr = Ws + i * 36;
#pragma unroll
            for (int k = 0; k < 9; k++) {
                unsigned long long wa, wb;
                lds_v2u64(wr + 4 * k, wa, wb);
                fma2(o2[2 * k], ff, wa);
                fma2(o2[2 * k + 1], ff, wb);
            }
        }
        float oc[36];
#pragma unroll
        for (int k = 0; k < 18; k++) unpack2(o2[k], oc[2 * k], oc[2 * k + 1]);
        float sd = 0.0f;
#pragma unroll
        for (int c = 0; c < 35; c++) sd += oc[c] * a2s[c];
        g_sdst[agg][base + tid] = sd;
        float* tr = tile + tid * 37;
#pragma unroll
        for (int c = 0; c < 35; c++) tr[c] = oc[c];
        tr[35] = 0.0f;                      // pad col must be 0
    }
    __syncthreads();

    // ---- coalesced float4 store of the 36-wide rows ----
    float* om = g_emb[agg] + (size_t)base * 36;
    for (int q = tid; q < cnt * 9; q += 128) {
        int r = q / 9, c4 = q - 9 * r;
        const float* tr = tile + r * 37 + c4 * 4;
        float4 v = make_float4(tr[0], tr[1], tr[2], tr[3]);
        *(float4*)(om + r * 36 + c4 * 4) = v;
    }
}

// ---------------------------------------------------------------------------
// Kernel 2: attention aggregation. One warp per (agg, node).
// (d*36, w) cached in shared; gather phase processes 3 edges/iteration
// with 27 active lanes (lanes g*9+q, q<9 fetch float4 of row dst[e]).
// ---------------------------------------------------------------------------
__global__ void __launch_bounds__(256) aggregate_kernel(Params p) {
    __shared__ int   sh_off[8][33];
    __shared__ float sh_w[8][33];
    const int wb   = threadIdx.x >> 5;
    const int lane = threadIdx.x & 31;
    const int gw   = blockIdx.x * 8 + wb;
    const int agg  = gw / N_NODES;
    const int node = gw - agg * N_NODES;

    int d = p.dst[agg][node * DEG + lane];
    float z  = g_ssrc[agg][node] + g_sdst[agg][d];
    float el = (z > 0.0f) ? z : 0.1f * expm1f(z);
    float w  = expf(el);

    float den = w;
#pragma unroll
    for (int off = 16; off; off >>= 1) den += __shfl_xor_sync(0xffffffffu, den, off);

    sh_off[wb][lane] = d * 36;
    sh_w[wb][lane]   = w;
    if (lane == 0) { sh_off[wb][32] = 0; sh_w[wb][32] = 0.0f; }
    __syncwarp();

    const int g = lane / 9;            // 0..2 active, 3 idle
    const int q = lane - 9 * g;
    float4 acc = make_float4(0.f, 0.f, 0.f, 0.f);
    if (g < 3) {
        const float* tab = g_emb[agg];
#pragma unroll
        for (int t = 0; t < 11; t++) {
            int e = 3 * t + g;                     // 0..32 (slot 32 has w=0)
            int   off = sh_off[wb][e];
            float we  = sh_w[wb][e];
            const float4 v = *(const float4*)(tab + off + q * 4);
            acc.x += we * v.x; acc.y += we * v.y;
            acc.z += we * v.z; acc.w += we * v.w;
        }
    }
    // fold groups 1,2 into group 0 (lanes 0..8)
    float r0 = acc.x + __shfl_down_sync(0xffffffffu, acc.x, 9) + __shfl_down_sync(0xffffffffu, acc.x, 18);
    float r1 = acc.y + __shfl_down_sync(0xffffffffu, acc.y, 9) + __shfl_down_sync(0xffffffffu, acc.y, 18);
    float r2 = acc.z + __shfl_down_sync(0xffffffffu, acc.z, 9) + __shfl_down_sync(0xffffffffu, acc.z, 18);
    float r3 = acc.w + __shfl_down_sync(0xffffffffu, acc.w, 9) + __shfl_down_sync(0xffffffffu, acc.w, 18);

    if (lane < 9) {
        float inv = 1.0f / den;
        float4 res = make_float4(r0 * inv, r1 * inv, r2 * inv, r3 * inv);
        *(float4*)(g_m[agg] + node * 36 + lane * 4) = res;
    }
}

// ---------------------------------------------------------------------------
// Kernel 3: update MLP 105->70(PReLU)->35, FFMA2 throughout.
// x kept as 54 packed f32x2 regs in padded layout [f 35|0|mp 35|0|mn 35|0];
// W1 transposed+permuted to match; all GMEM I/O staged coalesced.
// Dynamic shared (~58 KB): W1T[70*108] W2[70*36] b1[70] b2[36] tile[128*37].
// ---------------------------------------------------------------------------
#define UPD_W1T   0
#define UPD_W2    (70 * 108)
#define UPD_B1    (UPD_W2 + 70 * 36)
#define UPD_B2    (UPD_B1 + 72)
#define UPD_TILE  (UPD_B2 + 40)           // float index, %4==0 -> 16B aligned
#define UPD_FLOATS (UPD_TILE + 128 * 37)
#define UPD_SMEM_BYTES (UPD_FLOATS * 4)

__global__ void __launch_bounds__(128) update_kernel(Params p) {
    extern __shared__ __align__(16) float usm[];
    float* W1T  = usm + UPD_W1T;
    float* W2s  = usm + UPD_W2;
    float* b1s  = usm + UPD_B1;
    float* b2s  = usm + UPD_B2;
    float* tile = usm + UPD_TILE;
    const int tid = threadIdx.x;

    for (int t = tid; t < 70 * 108; t += 128) {
        int j = t / 108, s = t - 108 * j;
        int os = (s < 35) ? s : (s == 35) ? -1 : (s < 71) ? s - 1 : (s == 71) ? -1 : (s < 107) ? s - 2 : -1;
        W1T[t] = (os >= 0) ? p.W1[os * 70 + j] : 0.0f;
    }
    for (int t = tid; t < 70 * 36; t += 128) {
        int j = t / 36, c = t - 36 * j;
        W2s[t] = (c < 35) ? p.W2[j * 35 + c] : 0.0f;
    }
    for (int t = tid; t < 70; t += 128) b1s[t] = p.b1[t];
    for (int t = tid; t < 36; t += 128) b2s[t] = (t < 35) ? p.b2[t] : 0.0f;
    float alpha_v = p.alpha[0];

    const int NBLK = (N_NODES + 127) / 128;     // 391
    const bool sideA = (blockIdx.x < NBLK);
    const int  bx   = sideA ? blockIdx.x : blockIdx.x - NBLK;
    const int  base = bx * 128;
    const int  cnt  = min(128, N_NODES - base);
    const float* fsrc = sideA ? p.fa : p.fb;
    const float* mpg  = (sideA ? g_m[0] : g_m[2]);
    const float* mng  = (sideA ? g_m[1] : g_m[3]);

    unsigned long long xp[54];

    // segment 0: features (35-float rows, coalesced stage)
    __syncthreads();
    for (int idx = tid; idx < cnt * 35; idx += 128) {
        int r = idx / 35, c = idx - 35 * r;
        tile[r * 37 + c] = fsrc[base * 35 + idx];
    }
    __syncthreads();
    if (tid < cnt) {
        const float* xr = tile + tid * 37;
#pragma unroll
        for (int k = 0; k < 17; k++) xp[k] = pack2(xr[2 * k], xr[2 * k + 1]);
        xp[17] = pack2(xr[34], 0.0f);
    }
    __syncthreads();
    // segment 1: m_pos (36-float rows; only 35 needed)
    for (int idx = tid; idx < cnt * 35; idx += 128) {
        int r = idx / 35, c = idx - 35 * r;
        tile[r * 37 + c] = mpg[(base + r) * 36 + c];
    }
    __syncthreads();
    if (tid < cnt) {
        const float* xr = tile + tid * 37;
#pragma unroll
        for (int k = 0; k < 17; k++) xp[18 + k] = pack2(xr[2 * k], xr[2 * k + 1]);
        xp[35] = pack2(xr[34], 0.0f);
    }
    __syncthreads();
    // segment 2: m_neg
    for (int idx = tid; idx < cnt * 35; idx += 128) {
        int r = idx / 35, c = idx - 35 * r;
        tile[r * 37 + c] = mng[(base + r) * 36 + c];
    }
    __syncthreads();
    if (tid < cnt) {
        const float* xr = tile + tid * 37;
#pragma unroll
        for (int k = 0; k < 17; k++) xp[36 + k] = pack2(xr[2 * k], xr[2 * k + 1]);
        xp[53] = pack2(xr[34], 0.0f);
    }

    if (tid < cnt) {
        unsigned long long o2[18];
#pragma unroll
        for (int k = 0; k < 18; k++) o2[k] = pack2(b2s[2 * k], b2s[2 * k + 1]);

        for (int j = 0; j < 70; j++) {
            unsigned long long h2a = 0ull, h2b = 0ull;   // (0.f,0.f)
            const float* wr = W1T + j * 108;
#pragma unroll
            for (int qq = 0; qq < 27; qq++) {
                unsigned long long wa, wb;
                lds_v2u64(wr + 4 * qq, wa, wb);
                fma2(h2a, xp[2 * qq], wa);
                fma2(h2b, xp[2 * qq + 1], wb);
            }
            float a0, a1, b0, b1v;
            unpack2(h2a, a0, a1); unpack2(h2b, b0, b1v);
            float hj = b1s[j] + ((a0 + a1) + (b0 + b1v));
            hj = (hj > 0.0f) ? hj : alpha_v * hj;
            unsigned long long hh = pack2(hj, hj);
            const float* w2r = W2s + j * 36;
#pragma unroll
            for (int k = 0; k < 9; k++) {
                unsigned long long wa, wb;
                lds_v2u64(w2r + 4 * k, wa, wb);
                fma2(o2[2 * k], hh, wa);
                fma2(o2[2 * k + 1], hh, wb);
            }
        }
        // stage output row into tile
        float* tr = tile + tid * 37;
#pragma unroll
        for (int k = 0; k < 18; k++) {
            float lo, hi; unpack2(o2[k], lo, hi);
            if (2 * k     < 35) tr[2 * k]     = lo;
            if (2 * k + 1 < 35) tr[2 * k + 1] = hi;
        }
    }
    __syncthreads();

    const int gbase = (sideA ? 0 : N_NODES) + base;
    for (int idx = tid; idx < cnt * 35; idx += 128) {
        int r = idx / 35, c = idx - 35 * r;
        p.out[gbase * 35 + idx] = tile[r * 37 + c];
    }
}

// ---------------------------------------------------------------------------
extern "C" void kernel_launch(void* const* d_in, const int* in_sizes, int n_in,
                              void* d_out, int out_size) {
    Params p;
    p.fa = (const float*)d_in[0];
    p.fb = (const float*)d_in[1];
    p.dst[0] = (const int*)d_in[2];
    p.dst[1] = (const int*)d_in[3];
    p.dst[2] = (const int*)d_in[4];
    p.dst[3] = (const int*)d_in[5];
    for (int k = 0; k < 4; k++) {
        p.W[k]   = (const float*)d_in[6 + 3 * k];
        p.bv[k]  = (const float*)d_in[7 + 3 * k];
        p.att[k] = (const float*)d_in[8 + 3 * k];
    }
    p.W1    = (const float*)d_in[18];
    p.b1    = (const float*)d_in[19];
    p.alpha = (const float*)d_in[20];
    p.W2    = (const float*)d_in[21];
    p.b2    = (const float*)d_in[22];
    p.out   = (float*)d_out;

    dim3 g1((N_NODES + 127) / 128, 4);
    transform_kernel<<<g1, 128>>>(p);

    aggregate_kernel<<<(4 * N_NODES) / 8, 256>>>(p);

    cudaFuncSetAttribute(update_kernel, cudaFuncAttributeMaxDynamicSharedMemorySize, UPD_SMEM_BYTES);
    update_kernel<<<2 * ((N_NODES + 127) / 128), 128, UPD_SMEM_BYTES>>>(p);
}

// round 5
// speedup vs baseline: 1.0774x; 1.0437x over previous
#include <cuda_runtime.h>
#include <cuda_fp16.h>
#include <math.h>

#define N_NODES 50000
#define EMB 35
#define DEG 32

// Scratch (static __device__).
// g_emb: fp16 transformed tables, 40-half rows (80B), cols 35..39 = 0.
__device__ __half g_emb[4][N_NODES * 40];
__device__ float  g_sdst[4][N_NODES];
__device__ float  g_ssrc[4][N_NODES];
__device__ float  g_m[4][N_NODES * 40];    // fp32 messages, 40-wide (35..39 = 0)

struct Params {
    const float* fa; const float* fb;
    const int*   dst[4];
    const float* W[4]; const float* bv[4]; const float* att[4];
    const float* W1; const float* b1; const float* alpha; const float* W2; const float* b2;
    float* out;
};

// ---- packed f32x2 helpers (sm_103a FFMA2) ----------------------------------
__device__ __forceinline__ unsigned long long pack2(float lo, float hi) {
    unsigned long long r;
    asm("mov.b64 %0, {%1,%2};" : "=l"(r) : "f"(lo), "f"(hi));
    return r;
}
__device__ __forceinline__ void unpack2(unsigned long long v, float& lo, float& hi) {
    asm("mov.b64 {%0,%1}, %2;" : "=f"(lo), "=f"(hi) : "l"(v));
}
__device__ __forceinline__ void fma2(unsigned long long& d, unsigned long long a, unsigned long long b) {
    asm("fma.rn.f32x2 %0, %1, %2, %0;" : "+l"(d) : "l"(a), "l"(b));
}
__device__ __forceinline__ void lds_v2u64(const float* sp, unsigned long long& a, unsigned long long& b) {
    unsigned int addr = (unsigned int)__cvta_generic_to_shared(sp);
    asm("ld.shared.v2.u64 {%0,%1}, [%2];" : "=l"(a), "=l"(b) : "r"(addr));
}

// ---------------------------------------------------------------------------
// Kernel 1: per-agg transform + attention scores. Block = 128 rows.
// Staging through a stride-41 shared tile; incremental (r,c) indexing
// (no per-element div/mod); emb written out as coalesced fp16 uint2 chunks.
// ---------------------------------------------------------------------------
__global__ void __launch_bounds__(128) transform_kernel(Params p) {
    const int agg = blockIdx.y;
    __shared__ __align__(16) float Ws[35 * 36];     // padded cols, col35 = 0
    __shared__ float tile[128 * 41];
    __shared__ float bs[36], a1s[35], a2s[35];

    {
        const float* W = p.W[agg];
        for (int t = threadIdx.x; t < 35 * 36; t += 128) {
            int i = t / 36, c = t - 36 * i;
            Ws[t] = (c < 35) ? W[i * 35 + c] : 0.0f;
        }
        const float* bb = p.bv[agg];
        for (int t = threadIdx.x; t < 36; t += 128) bs[t] = (t < 35) ? bb[t] : 0.0f;
        const float* at = p.att[agg];
        for (int t = threadIdx.x; t < 35; t += 128) { a1s[t] = at[t]; a2s[t] = at[35 + t]; }
    }

    const int base = blockIdx.x * 128;
    const int cnt  = min(128, N_NODES - base);
    const int tid  = threadIdx.x;
    const float* ftab = (agg < 2) ? p.fb : p.fa;
    const float* fsc  = (agg < 2) ? p.fa : p.fb;

    // ---- phase A: s_src ----
    __syncthreads();
    {
        int idx = tid, r = tid / 35, c = tid - 35 * (tid / 35);
        for (; idx < cnt * 35; idx += 128) {
            tile[r * 41 + c] = fsc[base * 35 + idx];
            r += 3; c += 23; if (c >= 35) { c -= 35; r += 1; }
        }
    }
    __syncthreads();
    if (tid < cnt) {
        float s1 = 0.0f;
        const float* xr = tile + tid * 41;
#pragma unroll
        for (int i = 0; i < 35; i++) s1 += xr[i] * a1s[i];
        g_ssrc[agg][base + tid] = s1;
    }
    __syncthreads();

    // ---- phase B: new_emb = ftab @ W + b, s_dst ----
    {
        int idx = tid, r = tid / 35, c = tid - 35 * (tid / 35);
        for (; idx < cnt * 35; idx += 128) {
            tile[r * 41 + c] = ftab[base * 35 + idx];
            r += 3; c += 23; if (c >= 35) { c -= 35; r += 1; }
        }
    }
    __syncthreads();
    if (tid < cnt) {
        unsigned long long o2[18];
#pragma unroll
        for (int k = 0; k < 18; k++) o2[k] = pack2(bs[2 * k], bs[2 * k + 1]);
        const float* xr = tile + tid * 41;
#pragma unroll
        for (int i = 0; i < 35; i++) {
            float fi = xr[i];
            unsigned long long ff = pack2(fi, fi);
            const float* wr = Ws + i * 36;
#pragma unroll
            for (int k = 0; k < 9; k++) {
                unsigned long long wa, wb;
                lds_v2u64(wr + 4 * k, wa, wb);
                fma2(o2[2 * k], ff, wa);
                fma2(o2[2 * k + 1], ff, wb);
            }
        }
        float oc[36];
#pragma unroll
        for (int k = 0; k < 18; k++) unpack2(o2[k], oc[2 * k], oc[2 * k + 1]);
        float sd = 0.0f;
#pragma unroll
        for (int c = 0; c < 35; c++) sd += oc[c] * a2s[c];
        g_sdst[agg][base + tid] = sd;
        float* tr = tile + tid * 41;
#pragma unroll
        for (int c = 0; c < 35; c++) tr[c] = oc[c];
#pragma unroll
        for (int c = 35; c < 40; c++) tr[c] = 0.0f;   // pad halves 35..39
    }
    __syncthreads();

    // ---- coalesced fp16 store: 10 uint2 chunks (4 halves each) per row ----
    {
        __half* om = g_emb[agg];
        int idx = tid, r = tid / 10, k = tid - 10 * (tid / 10);
        for (; idx < cnt * 10; idx += 128) {
            const float* tr = tile + r * 41 + k * 4;
            __half2 h0 = __floats2half2_rn(tr[0], tr[1]);
            __half2 h1 = __floats2half2_rn(tr[2], tr[3]);
            uint2 u = make_uint2(*reinterpret_cast<unsigned int*>(&h0),
                                 *reinterpret_cast<unsigned int*>(&h1));
            *(uint2*)(om + (size_t)(base + r) * 40 + k * 4) = u;
            r += 12; k += 8; if (k >= 10) { k -= 10; r += 1; }
        }
    }
}

// ---------------------------------------------------------------------------
// Kernel 2: attention aggregation. One warp per (agg, node).
// fp16 table rows (80B = 3 L2 sectors). 6 lane-groups of 5 process 6 edges
// per iteration; each active lane loads 16B (8 halves) of its group's row.
// ---------------------------------------------------------------------------
__global__ void __launch_bounds__(256) aggregate_kernel(Params p) {
    __shared__ uint2 sh[8][36];           // {row offset in halves, w bits}
    const int wb   = threadIdx.x >> 5;
    const int lane = threadIdx.x & 31;
    const int gw   = blockIdx.x * 8 + wb;
    const int agg  = gw / N_NODES;
    const int node = gw - agg * N_NODES;

    int d = p.dst[agg][node * DEG + lane];
    float z  = g_ssrc[agg][node] + g_sdst[agg][d];
    float el = (z > 0.0f) ? z : 0.1f * expm1f(z);
    float w  = expf(el);

    float den = w;
#pragma unroll
    for (int off = 16; off; off >>= 1) den += __shfl_xor_sync(0xffffffffu, den, off);

    sh[wb][lane] = make_uint2((unsigned)(d * 40), __float_as_uint(w));
    if (lane < 4) sh[wb][32 + lane] = make_uint2(0u, 0u);   // pad edges: row 0, w=0
    __syncwarp();

    const int g = lane / 5;              // groups 0..5 active (30 lanes), 6 idle
    const int q = lane - 5 * g;
    float acc[8];
#pragma unroll
    for (int k = 0; k < 8; k++) acc[k] = 0.0f;

    if (g < 6) {
        const __half* tab = g_emb[agg];
#pragma unroll
        for (int t = 0; t < 6; t++) {
            uint2 ew = sh[wb][t * 6 + g];
            float we = __uint_as_float(ew.y);
            const uint4 v = *(const uint4*)(tab + ew.x + q * 8);
            const __half2* hp = (const __half2*)&v;
            float2 f0 = __half22float2(hp[0]);
            float2 f1 = __half22float2(hp[1]);
            float2 f2 = __half22float2(hp[2]);
            float2 f3 = __half22float2(hp[3]);
            acc[0] += we * f0.x; acc[1] += we * f0.y;
            acc[2] += we * f1.x; acc[3] += we * f1.y;
            acc[4] += we * f2.x; acc[5] += we * f2.y;
            acc[6] += we * f3.x; acc[7] += we * f3.y;
        }
    }

    // fold 6 groups -> group 0 (lanes 0..4). Capture-then-add keeps reads valid.
#pragma unroll
    for (int k = 0; k < 8; k++) {
        acc[k] += __shfl_down_sync(0xffffffffu, acc[k], 15);  // g<3 += g+3
        float b1 = __shfl_down_sync(0xffffffffu, acc[k], 5);
        float b2 = __shfl_down_sync(0xffffffffu, acc[k], 10);
        acc[k] += b1 + b2;
    }

    if (lane < 5) {
        float inv = 1.0f / den;
        float* om = g_m[agg] + (size_t)node * 40 + lane * 8;
        *(float4*)(om)     = make_float4(acc[0] * inv, acc[1] * inv, acc[2] * inv, acc[3] * inv);
        *(float4*)(om + 4) = make_float4(acc[4] * inv, acc[5] * inv, acc[6] * inv, acc[7] * inv);
    }
}

// ---------------------------------------------------------------------------
// Kernel 3: update MLP 105->70(PReLU)->35, FFMA2; x packed in regs,
// weights broadcast from shared; coalesced staged I/O, incremental indexing.
// ---------------------------------------------------------------------------
#define UPD_W1T   0
#define UPD_W2    (70 * 108)
#define UPD_B1    (UPD_W2 + 70 * 36)
#define UPD_B2    (UPD_B1 + 72)
#define UPD_TILE  (UPD_B2 + 40)
#define UPD_FLOATS (UPD_TILE + 128 * 37)
#define UPD_SMEM_BYTES (UPD_FLOATS * 4)

__global__ void __launch_bounds__(128) update_kernel(Params p) {
    extern __shared__ __align__(16) float usm[];
    float* W1T  = usm + UPD_W1T;
    float* W2s  = usm + UPD_W2;
    float* b1s  = usm + UPD_B1;
    float* b2s  = usm + UPD_B2;
    float* tile = usm + UPD_TILE;
    const int tid = threadIdx.x;

    for (int t = tid; t < 70 * 108; t += 128) {
        int j = t / 108, s = t - 108 * j;
        int os = (s < 35) ? s : (s == 35) ? -1 : (s < 71) ? s - 1 : (s == 71) ? -1 : (s < 107) ? s - 2 : -1;
        W1T[t] = (os >= 0) ? p.W1[os * 70 + j] : 0.0f;
    }
    for (int t = tid; t < 70 * 36; t += 128) {
        int j = t / 36, c = t - 36 * j;
        W2s[t] = (c < 35) ? p.W2[j * 35 + c] : 0.0f;
    }
    for (int t = tid; t < 70; t += 128) b1s[t] = p.b1[t];
    for (int t = tid; t < 36; t += 128) b2s[t] = (t < 35) ? p.b2[t] : 0.0f;
    float alpha_v = p.alpha[0];

    const int NBLK = (N_NODES + 127) / 128;
    const bool sideA = (blockIdx.x < NBLK);
    const int  bx   = sideA ? blockIdx.x : blockIdx.x - NBLK;
    const int  base = bx * 128;
    const int  cnt  = min(128, N_NODES - base);
    const float* fsrc = sideA ? p.fa : p.fb;
    const float* mpg  = (sideA ? g_m[0] : g_m[2]);
    const float* mng  = (sideA ? g_m[1] : g_m[3]);

    unsigned long long xp[54];

    // segment 0: features (35-packed rows)
    __syncthreads();
    {
        int idx = tid, r = tid / 35, c = tid - 35 * (tid / 35);
        for (; idx < cnt * 35; idx += 128) {
            tile[r * 37 + c] = fsrc[base * 35 + idx];
            r += 3; c += 23; if (c >= 35) { c -= 35; r += 1; }
        }
    }
    __syncthreads();
    if (tid < cnt) {
        const float* xr = tile + tid * 37;
#pragma unroll
        for (int k = 0; k < 17; k++) xp[k] = pack2(xr[2 * k], xr[2 * k + 1]);
        xp[17] = pack2(xr[34], 0.0f);
    }
    __syncthreads();
    // segment 1: m_pos (40-wide rows)
    {
        int idx = tid, r = tid / 35, c = tid - 35 * (tid / 35);
        for (; idx < cnt * 35; idx += 128) {
            tile[r * 37 + c] = mpg[(size_t)(base + r) * 40 + c];
            r += 3; c += 23; if (c >= 35) { c -= 35; r += 1; }
        }
    }
    __syncthreads();
    if (tid < cnt) {
        const float* xr = tile + tid * 37;
#pragma unroll
        for (int k = 0; k < 17; k++) xp[18 + k] = pack2(xr[2 * k], xr[2 * k + 1]);
        xp[35] = pack2(xr[34], 0.0f);
    }
    __syncthreads();
    // segment 2: m_neg
    {
        int idx = tid, r = tid / 35, c = tid - 35 * (tid / 35);
        for (; idx < cnt * 35; idx += 128) {
            tile[r * 37 + c] = mng[(size_t)(base + r) * 40 + c];
            r += 3; c += 23; if (c >= 35) { c -= 35; r += 1; }
        }
    }
    __syncthreads();
    if (tid < cnt) {
        const float* xr = tile + tid * 37;
#pragma unroll
        for (int k = 0; k < 17; k++) xp[36 + k] = pack2(xr[2 * k], xr[2 * k + 1]);
        xp[53] = pack2(xr[34], 0.0f);
    }

    if (tid < cnt) {
        unsigned long long o2[18];
#pragma unroll
        for (int k = 0; k < 18; k++) o2[k] = pack2(b2s[2 * k], b2s[2 * k + 1]);

        for (int j = 0; j < 70; j++) {
            unsigned long long h2a = 0ull, h2b = 0ull;
            const float* wr = W1T + j * 108;
#pragma unroll
            for (int qq = 0; qq < 27; qq++) {
                unsigned long long wa, wb;
                lds_v2u64(wr + 4 * qq, wa, wb);
                fma2(h2a, xp[2 * qq], wa);
                fma2(h2b, xp[2 * qq + 1], wb);
            }
            float a0, a1, b0, b1v;
            unpack2(h2a, a0, a1); unpack2(h2b, b0, b1v);
            float hj = b1s[j] + ((a0 + a1) + (b0 + b1v));
            hj = (hj > 0.0f) ? hj : alpha_v * hj;
            unsigned long long hh = pack2(hj, hj);
            const float* w2r = W2s + j * 36;
#pragma unroll
            for (int k = 0; k < 9; k++) {
                unsigned long long wa, wb;
                lds_v2u64(w2r + 4 * k, wa, wb);
                fma2(o2[2 * k], hh, wa);
                fma2(o2[2 * k + 1], hh, wb);
            }
        }
        float* tr = tile + tid * 37;
#pragma unroll
        for (int k = 0; k < 18; k++) {
            float lo, hi; unpack2(o2[k], lo, hi);
            if (2 * k     < 35) tr[2 * k]     = lo;
            if (2 * k + 1 < 35) tr[2 * k + 1] = hi;
        }
    }
    __syncthreads();

    const int gbase = (sideA ? 0 : N_NODES) + base;
    {
        int idx = tid, r = tid / 35, c = tid - 35 * (tid / 35);
        for (; idx < cnt * 35; idx += 128) {
            p.out[gbase * 35 + idx] = tile[r * 37 + c];
            r += 3; c += 23; if (c >= 35) { c -= 35; r += 1; }
        }
    }
}

// ---------------------------------------------------------------------------
extern "C" void kernel_launch(void* const* d_in, const int* in_sizes, int n_in,
                              void* d_out, int out_size) {
    Params p;
    p.fa = (const float*)d_in[0];
    p.fb = (const float*)d_in[1];
    p.dst[0] = (const int*)d_in[2];
    p.dst[1] = (const int*)d_in[3];
    p.dst[2] = (const int*)d_in[4];
    p.dst[3] = (const int*)d_in[5];
    for (int k = 0; k < 4; k++) {
        p.W[k]   = (const float*)d_in[6 + 3 * k];
        p.bv[k]  = (const float*)d_in[7 + 3 * k];
        p.att[k] = (const float*)d_in[8 + 3 * k];
    }
    p.W1    = (const float*)d_in[18];
    p.b1    = (const float*)d_in[19];
    p.alpha = (const float*)d_in[20];
    p.W2    = (const float*)d_in[21];
    p.b2    = (const float*)d_in[22];
    p.out   = (float*)d_out;

    dim3 g1((N_NODES + 127) / 128, 4);
    transform_kernel<<<g1, 128>>>(p);

    aggregate_kernel<<<(4 * N_NODES) / 8, 256>>>(p);

    cudaFuncSetAttribute(update_kernel, cudaFuncAttributeMaxDynamicSharedMemorySize, UPD_SMEM_BYTES);
    update_kernel<<<2 * ((N_NODES + 127) / 128), 128, UPD_SMEM_BYTES>>>(p);
}